// round 5
// baseline (speedup 1.0000x reference)
#include <cuda_runtime.h>
#include <math.h>

#define GRES 64
#define GR3 (GRES*GRES*GRES)
#define MAXB 8
#define NBINS 512            // 8x8x8 regions of 8^3 voxels
#define MAXPTS (1<<18)
#define NCH 678              // 3 + 30 + 621 + 24

__device__ float g_joints[MAXB * 24 * 3];
__device__ float g_A[MAXB * 24 * 12];
__device__ float g_pm[MAXB * 207];
__device__ float g_vsh[MAXB * 6890 * 3];
__device__ unsigned int g_hist[NBINS];
__device__ unsigned int g_off[NBINS];     // mutated by scatter -> becomes end
__device__ unsigned int g_start[NBINS];   // stable start
__device__ int g_perm[MAXPTS];

__constant__ int c_parents[24] = {-1,0,0,0,1,2,3,4,5,6,7,8,9,9,9,12,13,14,16,17,18,19,20,21};

// ---------------------------------------------------------------------------
// Region key: which 8^3-voxel region the (clamped) floor voxel falls in
// ---------------------------------------------------------------------------
__device__ __forceinline__ int point_key(const float* __restrict__ points, int p,
                                         float scale, float c0, float c1, float c2)
{
    float px = fmaf(points[p * 3 + 0], scale, c0);
    float py = fmaf(points[p * 3 + 1], scale, c1);
    float pz = fmaf(points[p * 3 + 2], scale, c2);
    float cx = ((px + 1.f) * (float)GRES - 1.f) * 0.5f;
    float cy = ((py + 1.f) * (float)GRES - 1.f) * 0.5f;
    float cz = ((pz + 1.f) * (float)GRES - 1.f) * 0.5f;
    int ix = min(max((int)floorf(cx), 0), 63);
    int iy = min(max((int)floorf(cy), 0), 63);
    int iz = min(max((int)floorf(cz), 0), 63);
    return ((ix >> 3) << 6) | ((iy >> 3) << 3) | (iz >> 3);
}

__global__ void zero_hist_kernel() {
    int i = blockIdx.x * blockDim.x + threadIdx.x;
    if (i < NBINS) g_hist[i] = 0u;
}

__global__ void hist_kernel(const float* __restrict__ points,
                            const float* __restrict__ scale_p,
                            const float* __restrict__ center, int total)
{
    int p = blockIdx.x * blockDim.x + threadIdx.x;
    if (p >= total) return;
    int key = point_key(points, p, *scale_p, center[0], center[1], center[2]);
    atomicAdd(&g_hist[key], 1u);
}

__global__ void scan_kernel()   // 1 block, 512 threads
{
    __shared__ unsigned int ssum[NBINS];
    int tid = threadIdx.x;
    unsigned int v = g_hist[tid];
    ssum[tid] = v;
    __syncthreads();
    for (int st = 1; st < NBINS; st <<= 1) {
        unsigned int t = (tid >= st) ? ssum[tid - st] : 0u;
        __syncthreads();
        ssum[tid] += t;
        __syncthreads();
    }
    unsigned int excl = ssum[tid] - v;
    g_off[tid] = excl;
    g_start[tid] = excl;
}

__global__ void scatter_kernel(const float* __restrict__ points,
                               const float* __restrict__ scale_p,
                               const float* __restrict__ center, int total)
{
    int p = blockIdx.x * blockDim.x + threadIdx.x;
    if (p >= total) return;
    int key = point_key(points, p, *scale_p, center[0], center[1], center[2]);
    unsigned int pos = atomicAdd(&g_off[key], 1u);
    g_perm[pos] = p;
}

// ---------------------------------------------------------------------------
__global__ void vshape_kernel(const float* __restrict__ beta,
                              const float* __restrict__ vt,
                              const float* __restrict__ sd, int B)
{
    int i = blockIdx.x * blockDim.x + threadIdx.x;
    int v = i % 6890, b = i / 6890;
    if (b >= B) return;
    const float* bb = beta + b * 10;
    const float* sdp = sd + v * 30;
    float v0 = vt[v * 3 + 0], v1 = vt[v * 3 + 1], v2 = vt[v * 3 + 2];
#pragma unroll
    for (int k = 0; k < 10; k++) {
        float bk = __ldg(bb + k);
        v0 = fmaf(sdp[k],      bk, v0);
        v1 = fmaf(sdp[10 + k], bk, v1);
        v2 = fmaf(sdp[20 + k], bk, v2);
    }
    float* o = g_vsh + (b * 6890 + v) * 3;
    o[0] = v0; o[1] = v1; o[2] = v2;
}

__global__ void joints_kernel(const float* __restrict__ JR)
{
    int jt = blockIdx.x, b = blockIdx.y;
    int tid = threadIdx.x;
    float a0 = 0.f, a1 = 0.f, a2 = 0.f;
    const float* vsh = g_vsh + b * 6890 * 3;
    for (int v = tid; v < 6890; v += blockDim.x) {
        float w = JR[jt * 6890 + v];
        a0 = fmaf(w, vsh[v * 3 + 0], a0);
        a1 = fmaf(w, vsh[v * 3 + 1], a1);
        a2 = fmaf(w, vsh[v * 3 + 2], a2);
    }
    __shared__ float r0[256], r1[256], r2[256];
    r0[tid] = a0; r1[tid] = a1; r2[tid] = a2;
    __syncthreads();
    for (int s = blockDim.x / 2; s > 0; s >>= 1) {
        if (tid < s) { r0[tid] += r0[tid + s]; r1[tid] += r1[tid + s]; r2[tid] += r2[tid + s]; }
        __syncthreads();
    }
    if (tid == 0) {
        float* o = g_joints + (b * 24 + jt) * 3;
        o[0] = r0[0]; o[1] = r1[0]; o[2] = r2[0];
    }
}

// ---------------------------------------------------------------------------
__global__ void transforms_kernel(const float* __restrict__ pose)
{
    int b = blockIdx.x;
    int i = threadIdx.x;
    __shared__ float rot[24][9];
    __shared__ float resR[24][9];
    __shared__ float resT[24][3];

    if (i < 24) {
        float rx = pose[b * 72 + i * 3 + 0];
        float ry = pose[b * 72 + i * 3 + 1];
        float rz = pose[b * 72 + i * 3 + 2];
        float th = sqrtf(rx * rx + ry * ry + rz * rz + 1e-12f);
        float inv = 1.f / th;
        float x = rx * inv, y = ry * inv, z = rz * inv;
        float s = sinf(th), c = cosf(th), t = 1.f - c;
        rot[i][0] = c + t * x * x;     rot[i][1] = t * x * y - s * z; rot[i][2] = t * x * z + s * y;
        rot[i][3] = t * x * y + s * z; rot[i][4] = c + t * y * y;     rot[i][5] = t * y * z - s * x;
        rot[i][6] = t * x * z - s * y; rot[i][7] = t * y * z + s * x; rot[i][8] = c + t * z * z;
    }
    __syncthreads();

    if (i >= 1 && i < 24) {
#pragma unroll
        for (int e = 0; e < 9; e++)
            g_pm[b * 207 + (i - 1) * 9 + e] = rot[i][e] - ((e == 0 || e == 4 || e == 8) ? 1.f : 0.f);
    }

    if (i == 0) {
        const float* J = g_joints + b * 72;
#pragma unroll
        for (int e = 0; e < 9; e++) resR[0][e] = rot[0][e];
        resT[0][0] = J[0]; resT[0][1] = J[1]; resT[0][2] = J[2];
        for (int jt = 1; jt < 24; jt++) {
            int p = c_parents[jt];
            float t0 = J[jt * 3 + 0] - J[p * 3 + 0];
            float t1 = J[jt * 3 + 1] - J[p * 3 + 1];
            float t2 = J[jt * 3 + 2] - J[p * 3 + 2];
            for (int r = 0; r < 3; r++) {
                float p0 = resR[p][r * 3 + 0], p1 = resR[p][r * 3 + 1], p2 = resR[p][r * 3 + 2];
                for (int cc = 0; cc < 3; cc++)
                    resR[jt][r * 3 + cc] = p0 * rot[jt][0 + cc] + p1 * rot[jt][3 + cc] + p2 * rot[jt][6 + cc];
                resT[jt][r] = p0 * t0 + p1 * t1 + p2 * t2 + resT[p][r];
            }
        }
        for (int jt = 0; jt < 24; jt++) {
            float jx = J[jt * 3 + 0], jy = J[jt * 3 + 1], jz = J[jt * 3 + 2];
            float* o = g_A + b * 288 + jt * 12;
            for (int r = 0; r < 3; r++) {
                float R0 = resR[jt][r * 3 + 0], R1 = resR[jt][r * 3 + 1], R2 = resR[jt][r * 3 + 2];
                o[r * 4 + 0] = R0; o[r * 4 + 1] = R1; o[r * 4 + 2] = R2;
                o[r * 4 + 3] = resT[jt][r] - (R0 * jx + R1 * jy + R2 * jz);
            }
        }
    }
}

// ---------------------------------------------------------------------------
// Main kernel: one block per 8^3-voxel region. Per channel: cooperatively
// stage the 9^3 halo brick in smem (double-buffered), points interp from smem.
// Brick layout: [9][9][10] floats (x*90 + y*10 + z).
// ---------------------------------------------------------------------------
__global__ void __launch_bounds__(256) main_kernel(
    const float* __restrict__ points,
    const float* __restrict__ beta,
    const float* __restrict__ trans,
    const float* __restrict__ scale_p,
    const float* __restrict__ center,
    const float* __restrict__ closest,
    const float* __restrict__ shd,
    const float* __restrict__ pdirs,
    const float* __restrict__ skin,
    float* __restrict__ out,
    int N, int B, int total)
{
    __shared__ float sb[2][9 * 90];     // 810 floats per buffer
    __shared__ float s_pm[MAXB][207];
    __shared__ float s_A[MAXB][288];
    __shared__ float s_beta[MAXB][10];
    __shared__ float s_trans[MAXB][3];

    int r = blockIdx.x;
    int start = (int)g_start[r];
    int end = (int)g_off[r];
    if (start >= end) return;

    int ox = ((r >> 6) & 7) << 3;
    int oy = ((r >> 3) & 7) << 3;
    int oz = (r & 7) << 3;

    for (int k = threadIdx.x; k < B * 508; k += blockDim.x) {
        int bb = k / 508, rr = k % 508;
        if (rr < 207)      s_pm[bb][rr]          = g_pm[bb * 207 + rr];
        else if (rr < 495) s_A[bb][rr - 207]     = g_A[bb * 288 + (rr - 207)];
        else if (rr < 505) s_beta[bb][rr - 495]  = beta[bb * 10 + (rr - 495)];
        else               s_trans[bb][rr - 505] = trans[bb * 3 + (rr - 505)];
    }
    __syncthreads();

    float scale = *scale_p;
    float c0 = center[0], c1 = center[1], c2 = center[2];

    auto chanptr = [&](int c) -> const float* {
        if (c < 3)   return closest + c * GR3;
        if (c < 33)  return shd + (c - 3) * GR3;
        if (c < 654) return pdirs + (c - 33) * GR3;
        return skin + (c - 654) * GR3;
    };

    auto fillb = [&](float* dst, const float* __restrict__ g) {
        for (int idx = threadIdx.x; idx < 729; idx += 256) {
            int x = idx / 81;
            int rem = idx - x * 81;
            int y = rem / 9;
            int z = rem - y * 9;
            int gx = min(ox + x, 63), gy = min(oy + y, 63), gz = min(oz + z, 63);
            dst[x * 90 + y * 10 + z] = __ldg(g + ((gx << 6) + gy) * 64 + gz);
        }
    };

    for (int tstart = start; tstart < end; tstart += 256) {
        int t = tstart + (int)threadIdx.x;
        bool valid = (t < end);
        int p = g_perm[valid ? t : start];
        int b = p / N;

        float px = fmaf(points[p * 3 + 0], scale, c0);
        float py = fmaf(points[p * 3 + 1], scale, c1);
        float pz = fmaf(points[p * 3 + 2], scale, c2);
        float cx = ((px + 1.f) * (float)GRES - 1.f) * 0.5f;
        float cy = ((py + 1.f) * (float)GRES - 1.f) * 0.5f;
        float cz = ((pz + 1.f) * (float)GRES - 1.f) * 0.5f;
        float fx = floorf(cx), fy = floorf(cy), fz = floorf(cz);
        int ix = (int)fx, iy = (int)fy, iz = (int)fz;
        float ux = cx - fx, uy = cy - fy, uz = cz - fz;

        float wx[2], wy[2], wz[2];
        int xi[2], yi[2], zi[2];
        wx[0] = (ix >= 0 && ix < GRES)         ? (1.f - ux) : 0.f;
        wx[1] = (ix + 1 >= 0 && ix + 1 < GRES) ? ux         : 0.f;
        wy[0] = (iy >= 0 && iy < GRES)         ? (1.f - uy) : 0.f;
        wy[1] = (iy + 1 >= 0 && iy + 1 < GRES) ? uy         : 0.f;
        wz[0] = (iz >= 0 && iz < GRES)         ? (1.f - uz) : 0.f;
        wz[1] = (iz + 1 >= 0 && iz + 1 < GRES) ? uz         : 0.f;
        xi[0] = min(max(ix, 0), 63);     xi[1] = min(max(ix + 1, 0), 63);
        yi[0] = min(max(iy, 0), 63);     yi[1] = min(max(iy + 1, 0), 63);
        zi[0] = min(max(iz, 0), 63);     zi[1] = min(max(iz + 1, 0), 63);

        // local brick offsets + weights (corner order: dx,dy,dz)
        int   l0, l1, l2, l3, l4, l5, l6, l7;
        float w0, w1, w2, w3, w4, w5, w6, w7;
        {
            int lx0 = xi[0] - ox, lx1 = xi[1] - ox;
            int ly0 = yi[0] - oy, ly1 = yi[1] - oy;
            int lz0 = zi[0] - oz, lz1 = zi[1] - oz;
            l0 = lx0 * 90 + ly0 * 10 + lz0;  w0 = wx[0] * wy[0] * wz[0];
            l1 = lx0 * 90 + ly0 * 10 + lz1;  w1 = wx[0] * wy[0] * wz[1];
            l2 = lx0 * 90 + ly1 * 10 + lz0;  w2 = wx[0] * wy[1] * wz[0];
            l3 = lx0 * 90 + ly1 * 10 + lz1;  w3 = wx[0] * wy[1] * wz[1];
            l4 = lx1 * 90 + ly0 * 10 + lz0;  w4 = wx[1] * wy[0] * wz[0];
            l5 = lx1 * 90 + ly0 * 10 + lz1;  w5 = wx[1] * wy[0] * wz[1];
            l6 = lx1 * 90 + ly1 * 10 + lz0;  w6 = wx[1] * wy[1] * wz[0];
            l7 = lx1 * 90 + ly1 * 10 + lz1;  w7 = wx[1] * wy[1] * wz[1];
        }

        float a0 = 0.f, a1 = 0.f, a2 = 0.f;
        float vx = 0.f, vy = 0.f, vz = 0.f;

        fillb(sb[0], chanptr(0));
        __syncthreads();

        for (int c = 0; c < NCH; c++) {
            if (c + 1 < NCH) fillb(sb[(c + 1) & 1], chanptr(c + 1));

            const float* br = sb[c & 1];
            float s00 = fmaf(w0, br[l0], w1 * br[l1]);
            float s01 = fmaf(w2, br[l2], w3 * br[l3]);
            float s10 = fmaf(w4, br[l4], w5 * br[l5]);
            float s11 = fmaf(w6, br[l6], w7 * br[l7]);
            float s = (s00 + s01) + (s10 + s11);

            if (c < 3) {
                if (c == 0) a0 += s; else if (c == 1) a1 += s; else a2 += s;
            } else if (c < 33) {
                int k = c - 3;
                int d = k / 10;
                float v = s * s_beta[b][k - d * 10];
                if (d == 0) a0 += v; else if (d == 1) a1 += v; else a2 += v;
            } else if (c < 654) {
                int k = c - 33;
                int d = k / 207;
                float v = s * s_pm[b][k - d * 207];
                if (d == 0) a0 += v; else if (d == 1) a1 += v; else a2 += v;
            } else {
                const float* Aj = &s_A[b][(c - 654) * 12];
                vx = fmaf(s, fmaf(Aj[0], a0, fmaf(Aj[1], a1, fmaf(Aj[2],  a2, Aj[3]))),  vx);
                vy = fmaf(s, fmaf(Aj[4], a0, fmaf(Aj[5], a1, fmaf(Aj[6],  a2, Aj[7]))),  vy);
                vz = fmaf(s, fmaf(Aj[8], a0, fmaf(Aj[9], a1, fmaf(Aj[10], a2, Aj[11]))), vz);
            }
            __syncthreads();
        }

        if (valid) {
            out[p * 3 + 0] = vx + s_trans[b][0];
            out[p * 3 + 1] = vy + s_trans[b][1];
            out[p * 3 + 2] = vz + s_trans[b][2];
        }
    }
}

// ---------------------------------------------------------------------------
extern "C" void kernel_launch(void* const* d_in, const int* in_sizes, int n_in,
                              void* d_out, int out_size)
{
    const float* points  = (const float*)d_in[0];
    const float* pose    = (const float*)d_in[1];
    const float* beta    = (const float*)d_in[2];
    const float* trans   = (const float*)d_in[3];
    const float* scale   = (const float*)d_in[4];
    const float* center  = (const float*)d_in[5];
    const float* closest = (const float*)d_in[6];
    const float* shd     = (const float*)d_in[7];
    const float* pdirs   = (const float*)d_in[8];
    const float* skin    = (const float*)d_in[9];
    const float* vt      = (const float*)d_in[10];
    const float* sd      = (const float*)d_in[11];
    const float* JR      = (const float*)d_in[12];

    int B = in_sizes[1] / 72;
    int N = in_sizes[0] / (3 * B);
    int total = B * N;
    int pblocks256 = (total + 255) / 256;

    zero_hist_kernel<<<(NBINS + 255) / 256, 256>>>();
    hist_kernel<<<pblocks256, 256>>>(points, scale, center, total);
    scan_kernel<<<1, NBINS>>>();
    scatter_kernel<<<pblocks256, 256>>>(points, scale, center, total);

    vshape_kernel<<<(6890 * B + 255) / 256, 256>>>(beta, vt, sd, B);
    dim3 jg(24, B);
    joints_kernel<<<jg, 256>>>(JR);
    transforms_kernel<<<B, 32>>>(pose);

    main_kernel<<<NBINS, 256>>>(points, beta, trans, scale, center,
                                closest, shd, pdirs, skin,
                                (float*)d_out, N, B, total);
}

// round 9
// speedup vs baseline: 1.7566x; 1.7566x over previous
#include <cuda_runtime.h>
#include <math.h>

#define GRES 64
#define GR3 (GRES*GRES*GRES)
#define MAXB 8
#define NBINS 32768          // 32^3 morton cells (2-voxel cells)
#define NREG 512             // 8^3 regions = morton key >> 6
#define MAXPTS (1<<18)
#define NCH 678              // 3 + 30 + 621 + 24
#define CHUNK 16
#define BRICK 810            // [9][9][10] floats, x*90+y*10+z

__device__ float g_joints[MAXB * 24 * 3];
__device__ float g_A[MAXB * 24 * 12];
__device__ float g_pm[MAXB * 207];
__device__ float g_vsh[MAXB * 6890 * 3];
__device__ unsigned int g_hist[NBINS];
__device__ unsigned int g_off[NBINS];
__device__ unsigned int g_rstart[NREG + 1];
__device__ int g_perm[MAXPTS];

__constant__ int c_parents[24] = {-1,0,0,0,1,2,3,4,5,6,7,8,9,9,9,12,13,14,16,17,18,19,20,21};

// ---------------------------------------------------------------------------
// 15-bit morton key of the 2-voxel cell; key>>6 = 8^3-voxel region id
// ---------------------------------------------------------------------------
__device__ __forceinline__ int point_key(const float* __restrict__ points, int p,
                                         float scale, float c0, float c1, float c2)
{
    float px = fmaf(points[p * 3 + 0], scale, c0);
    float py = fmaf(points[p * 3 + 1], scale, c1);
    float pz = fmaf(points[p * 3 + 2], scale, c2);
    float cx = ((px + 1.f) * (float)GRES - 1.f) * 0.5f;
    float cy = ((py + 1.f) * (float)GRES - 1.f) * 0.5f;
    float cz = ((pz + 1.f) * (float)GRES - 1.f) * 0.5f;
    unsigned x = (unsigned)(min(max((int)floorf(cx), 0), 63)) >> 1;
    unsigned y = (unsigned)(min(max((int)floorf(cy), 0), 63)) >> 1;
    unsigned z = (unsigned)(min(max((int)floorf(cz), 0), 63)) >> 1;
    unsigned key = 0;
#pragma unroll
    for (int b = 0; b < 5; b++) {
        key |= ((x >> b) & 1u) << (3 * b + 2);
        key |= ((y >> b) & 1u) << (3 * b + 1);
        key |= ((z >> b) & 1u) << (3 * b + 0);
    }
    return (int)key;
}

__global__ void hist_kernel(const float* __restrict__ points,
                            const float* __restrict__ scale_p,
                            const float* __restrict__ center, int total)
{
    int p = blockIdx.x * blockDim.x + threadIdx.x;
    if (p >= total) return;
    int key = point_key(points, p, *scale_p, center[0], center[1], center[2]);
    atomicAdd(&g_hist[key], 1u);
}

// Exclusive scan over 32k bins; also records region starts (every 64 bins)
// and self-zeroes g_hist for the next launch. One block, 1024 threads.
__global__ void scan_kernel()
{
    __shared__ unsigned int ssum[1024];
    int tid = threadIdx.x;
    unsigned int local[32];
    unsigned int s = 0;
#pragma unroll
    for (int i = 0; i < 32; i++) { local[i] = s; s += g_hist[tid * 32 + i]; }
    ssum[tid] = s;
    __syncthreads();
    for (int st = 1; st < 1024; st <<= 1) {
        unsigned int v = (tid >= st) ? ssum[tid - st] : 0u;
        __syncthreads();
        ssum[tid] += v;
        __syncthreads();
    }
    unsigned int base = (tid == 0) ? 0u : ssum[tid - 1];
#pragma unroll
    for (int i = 0; i < 32; i++) {
        g_off[tid * 32 + i] = base + local[i];
        g_hist[tid * 32 + i] = 0u;             // self-zero for next launch
    }
    if ((tid & 1) == 0) g_rstart[tid >> 1] = base;   // bin tid*32 is region (tid/2)*64
    if (tid == 1023)    g_rstart[NREG] = ssum[1023];
}

__global__ void scatter_kernel(const float* __restrict__ points,
                               const float* __restrict__ scale_p,
                               const float* __restrict__ center, int total)
{
    int p = blockIdx.x * blockDim.x + threadIdx.x;
    if (p >= total) return;
    int key = point_key(points, p, *scale_p, center[0], center[1], center[2]);
    unsigned int pos = atomicAdd(&g_off[key], 1u);
    g_perm[pos] = p;
}

// ---------------------------------------------------------------------------
__global__ void vshape_kernel(const float* __restrict__ beta,
                              const float* __restrict__ vt,
                              const float* __restrict__ sd, int B)
{
    int i = blockIdx.x * blockDim.x + threadIdx.x;
    int v = i % 6890, b = i / 6890;
    if (b >= B) return;
    const float* bb = beta + b * 10;
    const float* sdp = sd + v * 30;
    float v0 = vt[v * 3 + 0], v1 = vt[v * 3 + 1], v2 = vt[v * 3 + 2];
#pragma unroll
    for (int k = 0; k < 10; k++) {
        float bk = __ldg(bb + k);
        v0 = fmaf(sdp[k],      bk, v0);
        v1 = fmaf(sdp[10 + k], bk, v1);
        v2 = fmaf(sdp[20 + k], bk, v2);
    }
    float* o = g_vsh + (b * 6890 + v) * 3;
    o[0] = v0; o[1] = v1; o[2] = v2;
}

// ---------------------------------------------------------------------------
// Fused: joints (warp per joint, shuffle reduce) + rodrigues + chain + A rows
// grid (B), 768 threads (24 warps)
// ---------------------------------------------------------------------------
__global__ void skel_kernel(const float* __restrict__ pose,
                            const float* __restrict__ JR)
{
    int b = blockIdx.x;
    int tid = threadIdx.x;
    int w = tid >> 5, lane = tid & 31;

    __shared__ float sj[24][3];
    __shared__ float rot[24][9];
    __shared__ float resR[24][9];
    __shared__ float resT[24][3];

    if (w < 24) {
        float a0 = 0.f, a1 = 0.f, a2 = 0.f;
        const float* vsh = g_vsh + b * 6890 * 3;
        const float* jr = JR + w * 6890;
        for (int v = lane; v < 6890; v += 32) {
            float wt = __ldg(jr + v);
            a0 = fmaf(wt, vsh[v * 3 + 0], a0);
            a1 = fmaf(wt, vsh[v * 3 + 1], a1);
            a2 = fmaf(wt, vsh[v * 3 + 2], a2);
        }
#pragma unroll
        for (int s = 16; s > 0; s >>= 1) {
            a0 += __shfl_xor_sync(0xffffffffu, a0, s);
            a1 += __shfl_xor_sync(0xffffffffu, a1, s);
            a2 += __shfl_xor_sync(0xffffffffu, a2, s);
        }
        if (lane == 0) { sj[w][0] = a0; sj[w][1] = a1; sj[w][2] = a2; }
    }
    __syncthreads();

    if (tid < 24) {
        int i = tid;
        float rx = pose[b * 72 + i * 3 + 0];
        float ry = pose[b * 72 + i * 3 + 1];
        float rz = pose[b * 72 + i * 3 + 2];
        float th = sqrtf(rx * rx + ry * ry + rz * rz + 1e-12f);
        float inv = 1.f / th;
        float x = rx * inv, y = ry * inv, z = rz * inv;
        float s = sinf(th), c = cosf(th), t = 1.f - c;
        rot[i][0] = c + t * x * x;     rot[i][1] = t * x * y - s * z; rot[i][2] = t * x * z + s * y;
        rot[i][3] = t * x * y + s * z; rot[i][4] = c + t * y * y;     rot[i][5] = t * y * z - s * x;
        rot[i][6] = t * x * z - s * y; rot[i][7] = t * y * z + s * x; rot[i][8] = c + t * z * z;
    }
    __syncthreads();

    if (tid >= 1 && tid < 24) {
#pragma unroll
        for (int e = 0; e < 9; e++)
            g_pm[b * 207 + (tid - 1) * 9 + e] = rot[tid][e] - ((e == 0 || e == 4 || e == 8) ? 1.f : 0.f);
    }

    if (tid == 0) {
#pragma unroll
        for (int e = 0; e < 9; e++) resR[0][e] = rot[0][e];
        resT[0][0] = sj[0][0]; resT[0][1] = sj[0][1]; resT[0][2] = sj[0][2];
        for (int jt = 1; jt < 24; jt++) {
            int p = c_parents[jt];
            float t0 = sj[jt][0] - sj[p][0];
            float t1 = sj[jt][1] - sj[p][1];
            float t2 = sj[jt][2] - sj[p][2];
            for (int r = 0; r < 3; r++) {
                float p0 = resR[p][r * 3 + 0], p1 = resR[p][r * 3 + 1], p2 = resR[p][r * 3 + 2];
                for (int cc = 0; cc < 3; cc++)
                    resR[jt][r * 3 + cc] = p0 * rot[jt][0 + cc] + p1 * rot[jt][3 + cc] + p2 * rot[jt][6 + cc];
                resT[jt][r] = p0 * t0 + p1 * t1 + p2 * t2 + resT[p][r];
            }
        }
        for (int jt = 0; jt < 24; jt++) {
            float jx = sj[jt][0], jy = sj[jt][1], jz = sj[jt][2];
            float* o = g_A + b * 288 + jt * 12;
            for (int r = 0; r < 3; r++) {
                float R0 = resR[jt][r * 3 + 0], R1 = resR[jt][r * 3 + 1], R2 = resR[jt][r * 3 + 2];
                o[r * 4 + 0] = R0; o[r * 4 + 1] = R1; o[r * 4 + 2] = R2;
                o[r * 4 + 3] = resT[jt][r] - (R0 * jx + R1 * jy + R2 * jz);
            }
        }
    }
}

// ---------------------------------------------------------------------------
// Main: one block per 8^3 region. 16-channel staged chunks in dynamic smem.
// ---------------------------------------------------------------------------
__global__ void __launch_bounds__(256) main_kernel(
    const float* __restrict__ points,
    const float* __restrict__ beta,
    const float* __restrict__ trans,
    const float* __restrict__ scale_p,
    const float* __restrict__ center,
    const float* __restrict__ closest,
    const float* __restrict__ shd,
    const float* __restrict__ pdirs,
    const float* __restrict__ skin,
    float* __restrict__ out,
    int N, int B, int total)
{
    extern __shared__ float smem[];
    float* sbrick = smem;                         // CHUNK * BRICK
    float* s_pm   = sbrick + CHUNK * BRICK;       // B*207
    float* s_A    = s_pm + B * 207;               // B*288
    float* s_beta = s_A + B * 288;                // B*10
    float* s_tr   = s_beta + B * 10;              // B*3

    int r = blockIdx.x;
    int start = (int)g_rstart[r];
    int end   = (int)g_rstart[r + 1];
    if (start >= end) return;

    // region origin from 9-bit region id (morton levels 2..4)
    int ox = ((((r >> 2) & 1) | (((r >> 5) & 1) << 1) | (((r >> 8) & 1) << 2))) << 3;
    int oy = ((((r >> 1) & 1) | (((r >> 4) & 1) << 1) | (((r >> 7) & 1) << 2))) << 3;
    int oz = ((((r >> 0) & 1) | (((r >> 3) & 1) << 1) | (((r >> 6) & 1) << 2))) << 3;

    for (int k = threadIdx.x; k < B * 508; k += blockDim.x) {
        int bb = k / 508, rr = k % 508;
        if (rr < 207)      s_pm[bb * 207 + rr]        = g_pm[bb * 207 + rr];
        else if (rr < 495) s_A[bb * 288 + rr - 207]   = g_A[bb * 288 + (rr - 207)];
        else if (rr < 505) s_beta[bb * 10 + rr - 495] = beta[bb * 10 + (rr - 495)];
        else               s_tr[bb * 3 + rr - 505]    = trans[bb * 3 + (rr - 505)];
    }

    // precomputed fill slots (geometry is channel-independent)
    int nf = (threadIdx.x < 729 - 512) ? 3 : 2;
    int soff[3], goff[3];
#pragma unroll
    for (int i = 0; i < 3; i++) {
        int idx = (int)threadIdx.x + i * 256;
        if (idx < 729) {
            int x = idx / 81;
            int rem = idx - x * 81;
            int y = rem / 9;
            int z = rem - y * 9;
            soff[i] = x * 90 + y * 10 + z;
            int gx = min(ox + x, 63), gy = min(oy + y, 63), gz = min(oz + z, 63);
            goff[i] = ((gx << 6) + gy) * 64 + gz;
        } else { soff[i] = 0; goff[i] = 0; }
    }

    float scale = *scale_p;
    float c0c = center[0], c1c = center[1], c2c = center[2];
    __syncthreads();

    for (int ts = start; ts < end; ts += 256) {
        int t = ts + (int)threadIdx.x;
        bool valid = (t < end);
        int p = g_perm[valid ? t : start];
        int b = p / N;

        float px = fmaf(points[p * 3 + 0], scale, c0c);
        float py = fmaf(points[p * 3 + 1], scale, c1c);
        float pz = fmaf(points[p * 3 + 2], scale, c2c);
        float cx = ((px + 1.f) * (float)GRES - 1.f) * 0.5f;
        float cy = ((py + 1.f) * (float)GRES - 1.f) * 0.5f;
        float cz = ((pz + 1.f) * (float)GRES - 1.f) * 0.5f;
        float fx = floorf(cx), fy = floorf(cy), fz = floorf(cz);
        int ix = (int)fx, iy = (int)fy, iz = (int)fz;
        float ux = cx - fx, uy = cy - fy, uz = cz - fz;

        float wx0 = (ix >= 0 && ix < GRES)         ? (1.f - ux) : 0.f;
        float wx1 = (ix + 1 >= 0 && ix + 1 < GRES) ? ux         : 0.f;
        float wy0 = (iy >= 0 && iy < GRES)         ? (1.f - uy) : 0.f;
        float wy1 = (iy + 1 >= 0 && iy + 1 < GRES) ? uy         : 0.f;
        float wz0 = (iz >= 0 && iz < GRES)         ? (1.f - uz) : 0.f;
        float wz1 = (iz + 1 >= 0 && iz + 1 < GRES) ? uz         : 0.f;
        int lx0 = min(max(ix, 0), 63) - ox,     lx1 = min(max(ix + 1, 0), 63) - ox;
        int ly0 = min(max(iy, 0), 63) - oy,     ly1 = min(max(iy + 1, 0), 63) - oy;
        int lz0 = min(max(iz, 0), 63) - oz,     lz1 = min(max(iz + 1, 0), 63) - oz;

        int l0 = lx0 * 90 + ly0 * 10 + lz0;  float w0 = wx0 * wy0 * wz0;
        int l1 = l0 + (lz1 - lz0);           float w1 = wx0 * wy0 * wz1;
        int l2 = lx0 * 90 + ly1 * 10 + lz0;  float w2 = wx0 * wy1 * wz0;
        int l3 = l2 + (lz1 - lz0);           float w3 = wx0 * wy1 * wz1;
        int l4 = lx1 * 90 + ly0 * 10 + lz0;  float w4 = wx1 * wy0 * wz0;
        int l5 = l4 + (lz1 - lz0);           float w5 = wx1 * wy0 * wz1;
        int l6 = lx1 * 90 + ly1 * 10 + lz0;  float w6 = wx1 * wy1 * wz0;
        int l7 = l6 + (lz1 - lz0);           float w7 = wx1 * wy1 * wz1;

        float a0 = 0.f, a1 = 0.f, a2 = 0.f;
        float vx = 0.f, vy = 0.f, vz = 0.f;

        for (int cb = 0; cb < NCH; cb += CHUNK) {
            int cn = min(CHUNK, NCH - cb);
            // ---- fill 16 bricks ----
            for (int j = 0; j < cn; j++) {
                int c = cb + j;
                const float* gch;
                if (c < 3)        gch = closest + c * GR3;
                else if (c < 33)  gch = shd + (c - 3) * GR3;
                else if (c < 654) gch = pdirs + (c - 33) * GR3;
                else              gch = skin + (c - 654) * GR3;
                float* dst = sbrick + j * BRICK;
#pragma unroll
                for (int i = 0; i < 3; i++)
                    if (i < nf) dst[soff[i]] = __ldg(gch + goff[i]);
            }
            __syncthreads();
            // ---- consume 16 channels ----
            for (int j = 0; j < cn; j++) {
                int c = cb + j;
                const float* br = sbrick + j * BRICK;
                float s00 = fmaf(w0, br[l0], w1 * br[l1]);
                float s01 = fmaf(w2, br[l2], w3 * br[l3]);
                float s10 = fmaf(w4, br[l4], w5 * br[l5]);
                float s11 = fmaf(w6, br[l6], w7 * br[l7]);
                float s = (s00 + s01) + (s10 + s11);

                if (c < 3) {
                    if (c == 0) a0 += s; else if (c == 1) a1 += s; else a2 += s;
                } else if (c < 33) {
                    int k = c - 3;
                    int d = k / 10;
                    float v = s * s_beta[b * 10 + (k - d * 10)];
                    if (d == 0) a0 += v; else if (d == 1) a1 += v; else a2 += v;
                } else if (c < 654) {
                    int k = c - 33;
                    int d = k / 207;
                    float v = s * s_pm[b * 207 + (k - d * 207)];
                    if (d == 0) a0 += v; else if (d == 1) a1 += v; else a2 += v;
                } else {
                    const float* Aj = s_A + b * 288 + (c - 654) * 12;
                    vx = fmaf(s, fmaf(Aj[0], a0, fmaf(Aj[1], a1, fmaf(Aj[2],  a2, Aj[3]))),  vx);
                    vy = fmaf(s, fmaf(Aj[4], a0, fmaf(Aj[5], a1, fmaf(Aj[6],  a2, Aj[7]))),  vy);
                    vz = fmaf(s, fmaf(Aj[8], a0, fmaf(Aj[9], a1, fmaf(Aj[10], a2, Aj[11]))), vz);
                }
            }
            __syncthreads();
        }

        if (valid) {
            out[p * 3 + 0] = vx + s_tr[b * 3 + 0];
            out[p * 3 + 1] = vy + s_tr[b * 3 + 1];
            out[p * 3 + 2] = vz + s_tr[b * 3 + 2];
        }
    }
}

// ---------------------------------------------------------------------------
extern "C" void kernel_launch(void* const* d_in, const int* in_sizes, int n_in,
                              void* d_out, int out_size)
{
    const float* points  = (const float*)d_in[0];
    const float* pose    = (const float*)d_in[1];
    const float* beta    = (const float*)d_in[2];
    const float* trans   = (const float*)d_in[3];
    const float* scale   = (const float*)d_in[4];
    const float* center  = (const float*)d_in[5];
    const float* closest = (const float*)d_in[6];
    const float* shd     = (const float*)d_in[7];
    const float* pdirs   = (const float*)d_in[8];
    const float* skin    = (const float*)d_in[9];
    const float* vt      = (const float*)d_in[10];
    const float* sd      = (const float*)d_in[11];
    const float* JR      = (const float*)d_in[12];

    int B = in_sizes[1] / 72;
    int N = in_sizes[0] / (3 * B);
    int total = B * N;
    int pblocks = (total + 255) / 256;

    size_t smem_bytes = (size_t)(CHUNK * BRICK + B * (207 + 288 + 10 + 3)) * sizeof(float);
    static int attr_done = -1;
    if (attr_done != (int)smem_bytes) {   // idempotent, same value every call
        cudaFuncSetAttribute(main_kernel, cudaFuncAttributeMaxDynamicSharedMemorySize,
                             (int)smem_bytes);
        attr_done = (int)smem_bytes;
    }

    hist_kernel<<<pblocks, 256>>>(points, scale, center, total);
    scan_kernel<<<1, 1024>>>();
    scatter_kernel<<<pblocks, 256>>>(points, scale, center, total);
    vshape_kernel<<<(6890 * B + 255) / 256, 256>>>(beta, vt, sd, B);
    skel_kernel<<<B, 768>>>(pose, JR);
    main_kernel<<<NREG, 256, smem_bytes>>>(points, beta, trans, scale, center,
                                           closest, shd, pdirs, skin,
                                           (float*)d_out, N, B, total);
}